// round 11
// baseline (speedup 1.0000x reference)
#include <cuda_runtime.h>

#define NDAYS  4
#define NHOURS 24
#define NDH    96          // NDAYS*NHOURS
#define NDH4   24          // NDH/4
#define NLINKS 2000
#define NPATHS 20000
#define NODS   4000
#define MAXL   64          // max links per path (mean ~10)
#define MAXP   320         // max paths per link (mean ~100)

// ---------------- device scratch ----------------
// Invariant: g_plc, g_lpc, g_denom are ZERO at entry to every kernel_launch.
// CUDA zero-initializes __device__ globals at module load; each run restores
// zeros after last use, with NO added barriers:
//   g_plc  -> zeroed in k_scale (k_scale never reads it)
//   g_lpc  -> copied to g_lpc2 + zeroed in k_scale; k_out reads the copy
//   g_denom-> zeroed in k_out   (k_out never reads it)
__device__ float          g_V[NLINKS][NDH];       // V transposed: [link][dh]
__device__ float          g_ev[NPATHS][NDH];      // exp(vf)
__device__ float          g_f[NPATHS][NDH];       // f = pf * q
__device__ float          g_denom[NODS * NDH];    // sum of exp(vf) per (od, dh)
__device__ int            g_plc[NPATHS];          // links-per-path counts
__device__ unsigned short g_pl[NPATHS][MAXL];     // CSC: link ids per path
__device__ int            g_lpc[NLINKS];          // paths-per-link counts
__device__ int            g_lpc2[NLINKS];         // snapshot for k_out
__device__ unsigned short g_lp[NLINKS][MAXP];     // CSR: path ids per link

// ---------------- kernel 1: V prologue + scan D (160 MB) + build CSC/CSR ----------------
__device__ __forceinline__ void sp_append(int l, int p) {
    int c1 = atomicAdd(&g_plc[p], 1);
    if (c1 < MAXL) g_pl[p][c1] = (unsigned short)l;
    int c2 = atomicAdd(&g_lpc[l], 1);
    if (c2 < MAXP) g_lp[l][c2] = (unsigned short)p;
}

__device__ __forceinline__ void sp_proc(const uint4& v, int i, int pq) {
    if ((v.x | v.y | v.z | v.w) == 0u) return;
    int l = i / pq;
    int p = (i - l * pq) * 4;
    if (v.x) sp_append(l, p + 0);
    if (v.y) sp_append(l, p + 1);
    if (v.z) sp_append(l, p + 2);
    if (v.w) sp_append(l, p + 3);
}

__global__ void k_sparse(const uint4* __restrict__ D4,
                         const float* __restrict__ X,
                         const float* __restrict__ theta_raw,
                         const float* __restrict__ theta_links) {
    int tid = blockIdx.x * blockDim.x + threadIdx.x;

    // ---- prologue: compute V (0.77 MB of work, hides under the DRAM scan) ----
    if (tid < NDH * NLINKS) {
        int dh = tid / NLINKS;
        int l  = tid - dh * NLINKS;
        float t0 = fminf(theta_raw[0], 0.0f);
        float t1 = fminf(theta_raw[1], 0.0f);
        float t2 = fminf(theta_raw[2], 0.0f);
        float t3 = fminf(theta_raw[3], 0.0f);
        const float* xp = X + ((size_t)dh * NLINKS + l) * 5;
        g_V[l][dh] = xp[1] * t0 + xp[2] * t1 + xp[3] * t2 + xp[4] * t3 + theta_links[l];
    }

    // ---- main: streaming scan of D at 1-uint4 granularity, 4-way unrolled
    //      grid-stride (independent loads -> MLP=4, tail imbalance 1/32 spread) ----
    const int pq = NPATHS / 4;
    const int n4 = NLINKS * (NPATHS / 4);   // 10,000,000 uint4 slots
    const int S  = gridDim.x * blockDim.x;
    int t = tid;
    for (; t + 3 * S < n4; t += 4 * S) {
        uint4 v0 = __ldcs(&D4[t]);
        uint4 v1 = __ldcs(&D4[t + S]);
        uint4 v2 = __ldcs(&D4[t + 2 * S]);
        uint4 v3 = __ldcs(&D4[t + 3 * S]);
        sp_proc(v0, t,         pq);
        sp_proc(v1, t + S,     pq);
        sp_proc(v2, t + 2 * S, pq);
        sp_proc(v3, t + 3 * S, pq);
    }
    for (; t < n4; t += S) {
        uint4 v = __ldcs(&D4[t]);
        sp_proc(v, t, pq);
    }
}

// ---------------- kernel 2: vf gather -> ev + denom accumulation ----------------
// No max-subtraction needed: vf in ~[-60, +2], exp(vf) never under/overflows fp32.
__global__ void k_vf(const int* __restrict__ od_of_path) {
    int p  = blockIdx.x * 4 + threadIdx.y;   // block(96,4), grid 5000
    int dh = threadIdx.x;
    int cnt = min(g_plc[p], MAXL);
    const ushort4* pl4 = (const ushort4*)g_pl[p];
    float a0 = 0.f, a1 = 0.f, a2 = 0.f, a3 = 0.f;
    int i = 0;
    for (; i + 4 <= cnt; i += 4) {
        ushort4 l4 = pl4[i >> 2];
        a0 += g_V[l4.x][dh];
        a1 += g_V[l4.y][dh];
        a2 += g_V[l4.z][dh];
        a3 += g_V[l4.w][dh];
    }
    for (; i < cnt; ++i) a0 += g_V[g_pl[p][i]][dh];
    float ev = __expf((a0 + a1) + (a2 + a3));
    g_ev[p][dh] = ev;
    int od = od_of_path[p];
    atomicAdd(&g_denom[od * NDH + dh], ev);   // fire-and-forget RED
}

// ---------------- kernel 3: vectorized f = ev * q^2 / denom  (+ counter cleanup) ----------------
__global__ void k_scale(const float* __restrict__ q_sqrt,
                        const int*   __restrict__ od_of_path) {
    int idx = blockIdx.x * blockDim.x + threadIdx.x;   // NPATHS*NDH4 threads

    // cleanup (no reader of these in this kernel; pure stores)
    if (idx < NPATHS) g_plc[idx] = 0;                    // dead after k_vf
    if (idx < NLINKS) { g_lpc2[idx] = g_lpc[idx]; g_lpc[idx] = 0; }  // snapshot for k_out

    if (idx >= NPATHS * NDH4) return;
    int p  = idx / NDH4;
    int c  = (idx - p * NDH4) * 4;
    int od = od_of_path[p];
    float qv = q_sqrt[od];
    qv *= qv;
    float4 d = *(const float4*)&g_denom[od * NDH + c];
    float4 v = *(const float4*)&g_ev[p][c];
    float4 f;
    f.x = __fdividef(v.x * qv, d.x);
    f.y = __fdividef(v.y * qv, d.y);
    f.z = __fdividef(v.z * qv, d.z);
    f.w = __fdividef(v.w * qv, d.w);
    *(float4*)&g_f[p][c] = f;
}

// ---------------- kernel 4: x = relu(D f), BPR epilogue, write out ----------------
__global__ void k_out(const float* __restrict__ X,
                      const float* __restrict__ log_alpha,
                      const float* __restrict__ beta_raw,
                      const float* __restrict__ kcap,
                      float* __restrict__ out) {
    int l  = blockIdx.x * 2 + threadIdx.y;   // block(96,2), grid 1000
    int dh = threadIdx.x;

    // cleanup: g_denom dead after k_scale; fire-and-forget, no barrier needed
    {
        int gtid = l * NDH + dh;                 // 0..191999
        g_denom[gtid] = 0.0f;
        g_denom[gtid + NLINKS * NDH] = 0.0f;     // covers 192000..383999
    }

    int cnt = min(g_lpc2[l], MAXP);
    const ushort4* lp4 = (const ushort4*)g_lp[l];
    float a0 = 0.f, a1 = 0.f, a2 = 0.f, a3 = 0.f;
    int i = 0;
    for (; i + 4 <= cnt; i += 4) {
        ushort4 p4 = lp4[i >> 2];
        a0 += g_f[p4.x][dh];
        a1 += g_f[p4.y][dh];
        a2 += g_f[p4.z][dh];
        a3 += g_f[p4.w][dh];
    }
    for (; i < cnt; ++i) a0 += g_f[g_lp[l][i]][dh];
    float x = fmaxf((a0 + a1) + (a2 + a3), 0.0f);

    float alpha = __expf(log_alpha[l]);
    float beta  = fminf(fmaxf(beta_raw[l], 1e-12f), 4.0f);
    float tt    = X[((size_t)dh * NLINKS + l) * 5];   // X[...,0]
    float ratio = x / kcap[l];
    out[(size_t)dh * NLINKS + l] = tt * (1.0f + alpha * __powf(ratio, beta));
}

// ---------------- launcher ----------------
extern "C" void kernel_launch(void* const* d_in, const int* in_sizes, int n_in,
                              void* d_out, int out_size) {
    const float* X           = (const float*)d_in[0];
    const float* theta_raw   = (const float*)d_in[1];
    const float* theta_links = (const float*)d_in[2];
    const float* q_sqrt      = (const float*)d_in[3];
    const float* log_alpha   = (const float*)d_in[4];
    const float* beta_raw    = (const float*)d_in[5];
    const float* kcap        = (const float*)d_in[6];
    const float* D           = (const float*)d_in[7];
    const int*   od_of_path  = (const int*)d_in[8];
    float*       out         = (float*)d_out;

    k_sparse<<<1216, 256>>>((const uint4*)D, X, theta_raw, theta_links);
    k_vf<<<NPATHS / 4, dim3(NDH, 4)>>>(od_of_path);
    k_scale<<<(NPATHS * NDH4 + 255) / 256, 256>>>(q_sqrt, od_of_path);
    k_out<<<NLINKS / 2, dim3(NDH, 2)>>>(X, log_alpha, beta_raw, kcap, out);
}

// round 12
// speedup vs baseline: 1.0080x; 1.0080x over previous
#include <cuda_runtime.h>

#define NDAYS  4
#define NHOURS 24
#define NDH    96          // NDAYS*NHOURS
#define NDH4   24          // NDH/4
#define NLINKS 2000
#define NPATHS 20000
#define NODS   4000
#define MAXL   64          // max links per path (mean ~10)
#define MAXP   320         // max paths per link (mean ~100)

// ---------------- device scratch ----------------
// Invariant: g_plc, g_lpc, g_denom are ZERO at entry to every kernel_launch.
// CUDA zero-initializes __device__ globals at module load; each run restores
// zeros after last use, with NO added barriers:
//   g_plc  -> zeroed in k_scale (k_scale never reads it)
//   g_lpc  -> copied to g_lpc2 + zeroed in k_scale; k_out reads the copy
//   g_denom-> zeroed in k_out   (k_out never reads it)
__device__ float          g_V[NLINKS][NDH];       // V transposed: [link][dh]
__device__ float          g_ev[NPATHS][NDH];      // exp(vf)
__device__ float          g_f[NPATHS][NDH];       // f = pf * q
__device__ float          g_denom[NODS * NDH];    // sum of exp(vf) per (od, dh)
__device__ int            g_plc[NPATHS];          // links-per-path counts
__device__ unsigned short g_pl[NPATHS][MAXL];     // CSC: link ids per path
__device__ int            g_lpc[NLINKS];          // paths-per-link counts
__device__ int            g_lpc2[NLINKS];         // snapshot for k_out
__device__ unsigned short g_lp[NLINKS][MAXP];     // CSR: path ids per link

// ---------------- kernel 1: V prologue + scan D (160 MB) + build CSC/CSR ----------------
__device__ __forceinline__ void sp_append(int l, int p) {
    int c1 = atomicAdd(&g_plc[p], 1);
    if (c1 < MAXL) g_pl[p][c1] = (unsigned short)l;
    int c2 = atomicAdd(&g_lpc[l], 1);
    if (c2 < MAXP) g_lp[l][c2] = (unsigned short)p;
}

__device__ __forceinline__ void sp_proc(const uint4& v, int i, int pq) {
    if ((v.x | v.y | v.z | v.w) == 0u) return;
    int l = i / pq;
    int p = (i - l * pq) * 4;
    if (v.x) sp_append(l, p + 0);
    if (v.y) sp_append(l, p + 1);
    if (v.z) sp_append(l, p + 2);
    if (v.w) sp_append(l, p + 3);
}

__global__ void k_sparse(const uint4* __restrict__ D4,
                         const float* __restrict__ X,
                         const float* __restrict__ theta_raw,
                         const float* __restrict__ theta_links) {
    int tid = blockIdx.x * blockDim.x + threadIdx.x;

    // ---- prologue: compute V (0.77 MB of work, hides under the DRAM scan) ----
    if (tid < NDH * NLINKS) {
        int dh = tid / NLINKS;
        int l  = tid - dh * NLINKS;
        float t0 = fminf(theta_raw[0], 0.0f);
        float t1 = fminf(theta_raw[1], 0.0f);
        float t2 = fminf(theta_raw[2], 0.0f);
        float t3 = fminf(theta_raw[3], 0.0f);
        const float* xp = X + ((size_t)dh * NLINKS + l) * 5;
        g_V[l][dh] = xp[1] * t0 + xp[2] * t1 + xp[3] * t2 + xp[4] * t3 + theta_links[l];
    }

    // ---- main: streaming scan of D, 4 contiguous uint4 per slot (MLP=4) ----
    const int pq = NPATHS / 4;
    const int nt = (NLINKS * (NPATHS / 4)) / 4;   // 2.5M thread-slots of 4x uint4
    int S = gridDim.x * blockDim.x;
    for (int t = tid; t < nt; t += S) {
        int j = 4 * t;
        uint4 v0 = __ldcs(&D4[j + 0]);
        uint4 v1 = __ldcs(&D4[j + 1]);
        uint4 v2 = __ldcs(&D4[j + 2]);
        uint4 v3 = __ldcs(&D4[j + 3]);
        unsigned any = v0.x | v0.y | v0.z | v0.w | v1.x | v1.y | v1.z | v1.w |
                       v2.x | v2.y | v2.z | v2.w | v3.x | v3.y | v3.z | v3.w;
        if (any == 0u) continue;
        sp_proc(v0, j + 0, pq);
        sp_proc(v1, j + 1, pq);
        sp_proc(v2, j + 2, pq);
        sp_proc(v3, j + 3, pq);
    }
}

// ---------------- kernel 2: vf gather -> ev + denom accumulation ----------------
// No max-subtraction needed: vf in ~[-60, +2], exp(vf) never under/overflows fp32.
__global__ void k_vf(const int* __restrict__ od_of_path) {
    int p  = blockIdx.x * 4 + threadIdx.y;   // block(96,4), grid 5000
    int dh = threadIdx.x;
    int cnt = min(g_plc[p], MAXL);
    const ushort4* pl4 = (const ushort4*)g_pl[p];
    float a0 = 0.f, a1 = 0.f, a2 = 0.f, a3 = 0.f;
    int i = 0;
    for (; i + 4 <= cnt; i += 4) {
        ushort4 l4 = pl4[i >> 2];
        a0 += g_V[l4.x][dh];
        a1 += g_V[l4.y][dh];
        a2 += g_V[l4.z][dh];
        a3 += g_V[l4.w][dh];
    }
    for (; i < cnt; ++i) a0 += g_V[g_pl[p][i]][dh];
    float ev = __expf((a0 + a1) + (a2 + a3));
    g_ev[p][dh] = ev;
    int od = od_of_path[p];
    atomicAdd(&g_denom[od * NDH + dh], ev);   // fire-and-forget RED
}

// ---------------- kernel 3: vectorized f = ev * q^2 / denom  (+ counter cleanup) ----------------
__global__ void k_scale(const float* __restrict__ q_sqrt,
                        const int*   __restrict__ od_of_path) {
    int idx = blockIdx.x * blockDim.x + threadIdx.x;   // NPATHS*NDH4 threads

    // cleanup (no reader of these in this kernel; pure stores)
    if (idx < NPATHS) g_plc[idx] = 0;                    // dead after k_vf
    if (idx < NLINKS) { g_lpc2[idx] = g_lpc[idx]; g_lpc[idx] = 0; }  // snapshot for k_out

    if (idx >= NPATHS * NDH4) return;
    int p  = idx / NDH4;
    int c  = (idx - p * NDH4) * 4;
    int od = od_of_path[p];
    float qv = q_sqrt[od];
    qv *= qv;
    float4 d = *(const float4*)&g_denom[od * NDH + c];
    float4 v = *(const float4*)&g_ev[p][c];
    float4 f;
    f.x = __fdividef(v.x * qv, d.x);
    f.y = __fdividef(v.y * qv, d.y);
    f.z = __fdividef(v.z * qv, d.z);
    f.w = __fdividef(v.w * qv, d.w);
    *(float4*)&g_f[p][c] = f;
}

// ---------------- kernel 4: x = relu(D f), BPR epilogue, write out ----------------
// One block per link (grid 2000, block 96): path list staged in smem once,
// then unroll-4 gathers of g_f. (Empirically the fastest k_out shape: R2.)
__global__ void k_out(const float* __restrict__ X,
                      const float* __restrict__ log_alpha,
                      const float* __restrict__ beta_raw,
                      const float* __restrict__ kcap,
                      float* __restrict__ out) {
    __shared__ unsigned short ps[MAXP];
    __shared__ int scnt;
    int l  = blockIdx.x;          // grid 2000
    int dh = threadIdx.x;         // block 96

    // cleanup: g_denom dead after k_scale; fire-and-forget stores
    {
        int gtid = l * NDH + dh;                 // 0..191999
        g_denom[gtid] = 0.0f;
        g_denom[gtid + NLINKS * NDH] = 0.0f;     // covers 192000..383999
    }

    if (dh == 0) scnt = min(g_lpc2[l], MAXP);
    __syncthreads();
    int cnt = scnt;
    for (int i = dh; i < cnt; i += NDH) ps[i] = g_lp[l][i];
    __syncthreads();

    float a0 = 0.f, a1 = 0.f, a2 = 0.f, a3 = 0.f;
    int i = 0;
    for (; i + 4 <= cnt; i += 4) {
        int p0 = ps[i + 0];
        int p1 = ps[i + 1];
        int p2 = ps[i + 2];
        int p3 = ps[i + 3];
        a0 += g_f[p0][dh];
        a1 += g_f[p1][dh];
        a2 += g_f[p2][dh];
        a3 += g_f[p3][dh];
    }
    for (; i < cnt; ++i) a0 += g_f[ps[i]][dh];
    float x = fmaxf((a0 + a1) + (a2 + a3), 0.0f);

    float alpha = __expf(log_alpha[l]);
    float beta  = fminf(fmaxf(beta_raw[l], 1e-12f), 4.0f);
    float tt    = X[((size_t)dh * NLINKS + l) * 5];   // X[...,0]
    float ratio = x / kcap[l];
    out[(size_t)dh * NLINKS + l] = fmaf(tt * alpha, __powf(ratio, beta), tt);
}

// ---------------- launcher ----------------
extern "C" void kernel_launch(void* const* d_in, const int* in_sizes, int n_in,
                              void* d_out, int out_size) {
    const float* X           = (const float*)d_in[0];
    const float* theta_raw   = (const float*)d_in[1];
    const float* theta_links = (const float*)d_in[2];
    const float* q_sqrt      = (const float*)d_in[3];
    const float* log_alpha   = (const float*)d_in[4];
    const float* beta_raw    = (const float*)d_in[5];
    const float* kcap        = (const float*)d_in[6];
    const float* D           = (const float*)d_in[7];
    const int*   od_of_path  = (const int*)d_in[8];
    float*       out         = (float*)d_out;

    k_sparse<<<1216, 256>>>((const uint4*)D, X, theta_raw, theta_links);
    k_vf<<<NPATHS / 4, dim3(NDH, 4)>>>(od_of_path);
    k_scale<<<(NPATHS * NDH4 + 255) / 256, 256>>>(q_sqrt, od_of_path);
    k_out<<<NLINKS, NDH>>>(X, log_alpha, beta_raw, kcap, out);
}

// round 13
// speedup vs baseline: 1.0292x; 1.0210x over previous
#include <cuda_runtime.h>

#define NDAYS  4
#define NHOURS 24
#define NDH    96          // NDAYS*NHOURS
#define NDH8   12          // NDH/8
#define NLINKS 2000
#define NPATHS 20000
#define NODS   4000
#define MAXL   64          // max links per path (mean ~10)
#define MAXP   320         // max paths per link (mean ~100)

// ---------------- device scratch ----------------
// Invariant: g_plc, g_lpc, g_denom are ZERO at entry to every kernel_launch.
// CUDA zero-initializes __device__ globals at module load; each run restores
// zeros after last use, with NO added barriers:
//   g_plc  -> zeroed in k_scale (k_scale never reads it)
//   g_lpc  -> copied to g_lpc2 + zeroed in k_scale; k_out reads the copy
//   g_denom-> zeroed in k_out   (k_out never reads it)
__device__ float          g_V[NLINKS][NDH];       // V transposed: [link][dh]
__device__ float          g_ev[NPATHS][NDH];      // exp(vf)
__device__ float          g_f[NPATHS][NDH];       // f = pf * q
__device__ float          g_denom[NODS * NDH];    // sum of exp(vf) per (od, dh)
__device__ int            g_plc[NPATHS];          // links-per-path counts
__device__ unsigned short g_pl[NPATHS][MAXL];     // CSC: link ids per path
__device__ int            g_lpc[NLINKS];          // paths-per-link counts
__device__ int            g_lpc2[NLINKS];         // snapshot for k_out
__device__ unsigned short g_lp[NLINKS][MAXP];     // CSR: path ids per link

// ---------------- kernel 1: V prologue + scan D (160 MB) + build CSC/CSR ----------------
__device__ __forceinline__ void sp_append(int l, int p) {
    int c1 = atomicAdd(&g_plc[p], 1);
    if (c1 < MAXL) g_pl[p][c1] = (unsigned short)l;
    int c2 = atomicAdd(&g_lpc[l], 1);
    if (c2 < MAXP) g_lp[l][c2] = (unsigned short)p;
}

__device__ __forceinline__ void sp_proc(const uint4& v, int i, int pq) {
    if ((v.x | v.y | v.z | v.w) == 0u) return;
    int l = i / pq;
    int p = (i - l * pq) * 4;
    if (v.x) sp_append(l, p + 0);
    if (v.y) sp_append(l, p + 1);
    if (v.z) sp_append(l, p + 2);
    if (v.w) sp_append(l, p + 3);
}

__global__ void k_sparse(const uint4* __restrict__ D4,
                         const float* __restrict__ X,
                         const float* __restrict__ theta_raw,
                         const float* __restrict__ theta_links) {
    int tid = blockIdx.x * blockDim.x + threadIdx.x;

    // ---- prologue: compute V (0.77 MB of work, hides under the DRAM scan) ----
    if (tid < NDH * NLINKS) {
        int dh = tid / NLINKS;
        int l  = tid - dh * NLINKS;
        float t0 = fminf(theta_raw[0], 0.0f);
        float t1 = fminf(theta_raw[1], 0.0f);
        float t2 = fminf(theta_raw[2], 0.0f);
        float t3 = fminf(theta_raw[3], 0.0f);
        const float* xp = X + ((size_t)dh * NLINKS + l) * 5;
        g_V[l][dh] = xp[1] * t0 + xp[2] * t1 + xp[3] * t2 + xp[4] * t3 + theta_links[l];
    }

    // ---- main: streaming scan of D, 4 contiguous uint4 per slot (MLP=4) ----
    const int pq = NPATHS / 4;
    const int nt = (NLINKS * (NPATHS / 4)) / 4;   // 2.5M thread-slots of 4x uint4
    int S = gridDim.x * blockDim.x;
    for (int t = tid; t < nt; t += S) {
        int j = 4 * t;
        uint4 v0 = __ldcs(&D4[j + 0]);
        uint4 v1 = __ldcs(&D4[j + 1]);
        uint4 v2 = __ldcs(&D4[j + 2]);
        uint4 v3 = __ldcs(&D4[j + 3]);
        unsigned any = v0.x | v0.y | v0.z | v0.w | v1.x | v1.y | v1.z | v1.w |
                       v2.x | v2.y | v2.z | v2.w | v3.x | v3.y | v3.z | v3.w;
        if (any == 0u) continue;
        sp_proc(v0, j + 0, pq);
        sp_proc(v1, j + 1, pq);
        sp_proc(v2, j + 2, pq);
        sp_proc(v3, j + 3, pq);
    }
}

// ---------------- kernel 2: vf gather -> ev + denom, 2 paths per thread ----------------
// No max-subtraction needed: vf in ~[-60, +2], exp(vf) never under/overflows fp32.
// Each thread owns TWO paths (independent gathers -> 8 outstanding L2 loads).
// Counts are warp-uniform (one path pair per warp-row), so branches don't diverge.
__global__ void k_vf(const int* __restrict__ od_of_path) {
    int pA = blockIdx.x * 8 + threadIdx.y * 2;   // block(96,4), grid 2500
    int pB = pA + 1;
    int dh = threadIdx.x;

    int cA = min(g_plc[pA], MAXL);
    int cB = min(g_plc[pB], MAXL);
    const ushort4* a4 = (const ushort4*)g_pl[pA];
    const ushort4* b4 = (const ushort4*)g_pl[pB];

    float xA0 = 0.f, xA1 = 0.f, xA2 = 0.f, xA3 = 0.f;
    float xB0 = 0.f, xB1 = 0.f, xB2 = 0.f, xB3 = 0.f;
    int i = 0;
    for (; i + 4 <= cA || i + 4 <= cB; i += 4) {
        if (i + 4 <= cA) {
            ushort4 l4 = a4[i >> 2];
            xA0 += g_V[l4.x][dh];
            xA1 += g_V[l4.y][dh];
            xA2 += g_V[l4.z][dh];
            xA3 += g_V[l4.w][dh];
        }
        if (i + 4 <= cB) {
            ushort4 m4 = b4[i >> 2];
            xB0 += g_V[m4.x][dh];
            xB1 += g_V[m4.y][dh];
            xB2 += g_V[m4.z][dh];
            xB3 += g_V[m4.w][dh];
        }
    }
    for (int j = cA & ~3; j < cA; ++j) xA0 += g_V[g_pl[pA][j]][dh];
    for (int j = cB & ~3; j < cB; ++j) xB0 += g_V[g_pl[pB][j]][dh];

    float evA = __expf((xA0 + xA1) + (xA2 + xA3));
    float evB = __expf((xB0 + xB1) + (xB2 + xB3));
    g_ev[pA][dh] = evA;
    g_ev[pB][dh] = evB;
    atomicAdd(&g_denom[od_of_path[pA] * NDH + dh], evA);
    atomicAdd(&g_denom[od_of_path[pB] * NDH + dh], evB);
}

// ---------------- kernel 3: f = ev * q^2 / denom, 2 float4 per thread  (+ cleanup) ----------------
__global__ void k_scale(const float* __restrict__ q_sqrt,
                        const int*   __restrict__ od_of_path) {
    int idx = blockIdx.x * blockDim.x + threadIdx.x;   // NPATHS*NDH8 threads (240000)

    // cleanup (no reader of these in this kernel; pure stores)
    if (idx < NPATHS) g_plc[idx] = 0;                    // dead after k_vf
    if (idx < NLINKS) { g_lpc2[idx] = g_lpc[idx]; g_lpc[idx] = 0; }  // snapshot for k_out

    if (idx >= NPATHS * NDH8) return;
    int p  = idx / NDH8;
    int c  = (idx - p * NDH8) * 8;
    int od = od_of_path[p];
    float qv = q_sqrt[od];
    qv *= qv;
    float4 d0 = *(const float4*)&g_denom[od * NDH + c];
    float4 d1 = *(const float4*)&g_denom[od * NDH + c + 4];
    float4 v0 = *(const float4*)&g_ev[p][c];
    float4 v1 = *(const float4*)&g_ev[p][c + 4];
    float4 f0, f1;
    f0.x = __fdividef(v0.x * qv, d0.x);
    f0.y = __fdividef(v0.y * qv, d0.y);
    f0.z = __fdividef(v0.z * qv, d0.z);
    f0.w = __fdividef(v0.w * qv, d0.w);
    f1.x = __fdividef(v1.x * qv, d1.x);
    f1.y = __fdividef(v1.y * qv, d1.y);
    f1.z = __fdividef(v1.z * qv, d1.z);
    f1.w = __fdividef(v1.w * qv, d1.w);
    *(float4*)&g_f[p][c]     = f0;
    *(float4*)&g_f[p][c + 4] = f1;
}

// ---------------- kernel 4: x = relu(D f), BPR epilogue, write out ----------------
// One block per link (grid 2000, block 96): path list staged in smem once,
// then unroll-4 gathers of g_f. (Empirically the fastest k_out shape.)
__global__ void k_out(const float* __restrict__ X,
                      const float* __restrict__ log_alpha,
                      const float* __restrict__ beta_raw,
                      const float* __restrict__ kcap,
                      float* __restrict__ out) {
    __shared__ unsigned short ps[MAXP];
    __shared__ int scnt;
    int l  = blockIdx.x;          // grid 2000
    int dh = threadIdx.x;         // block 96

    // cleanup: g_denom dead after k_scale; fire-and-forget stores
    {
        int gtid = l * NDH + dh;                 // 0..191999
        g_denom[gtid] = 0.0f;
        g_denom[gtid + NLINKS * NDH] = 0.0f;     // covers 192000..383999
    }

    if (dh == 0) scnt = min(g_lpc2[l], MAXP);
    __syncthreads();
    int cnt = scnt;
    for (int i = dh; i < cnt; i += NDH) ps[i] = g_lp[l][i];
    __syncthreads();

    float a0 = 0.f, a1 = 0.f, a2 = 0.f, a3 = 0.f;
    int i = 0;
    for (; i + 4 <= cnt; i += 4) {
        int p0 = ps[i + 0];
        int p1 = ps[i + 1];
        int p2 = ps[i + 2];
        int p3 = ps[i + 3];
        a0 += g_f[p0][dh];
        a1 += g_f[p1][dh];
        a2 += g_f[p2][dh];
        a3 += g_f[p3][dh];
    }
    for (; i < cnt; ++i) a0 += g_f[ps[i]][dh];
    float x = fmaxf((a0 + a1) + (a2 + a3), 0.0f);

    float alpha = __expf(log_alpha[l]);
    float beta  = fminf(fmaxf(beta_raw[l], 1e-12f), 4.0f);
    float tt    = X[((size_t)dh * NLINKS + l) * 5];   // X[...,0]
    float ratio = x / kcap[l];
    out[(size_t)dh * NLINKS + l] = fmaf(tt * alpha, __powf(ratio, beta), tt);
}

// ---------------- launcher ----------------
extern "C" void kernel_launch(void* const* d_in, const int* in_sizes, int n_in,
                              void* d_out, int out_size) {
    const float* X           = (const float*)d_in[0];
    const float* theta_raw   = (const float*)d_in[1];
    const float* theta_links = (const float*)d_in[2];
    const float* q_sqrt      = (const float*)d_in[3];
    const float* log_alpha   = (const float*)d_in[4];
    const float* beta_raw    = (const float*)d_in[5];
    const float* kcap        = (const float*)d_in[6];
    const float* D           = (const float*)d_in[7];
    const int*   od_of_path  = (const int*)d_in[8];
    float*       out         = (float*)d_out;

    k_sparse<<<1216, 256>>>((const uint4*)D, X, theta_raw, theta_links);
    k_vf<<<NPATHS / 8, dim3(NDH, 4)>>>(od_of_path);
    k_scale<<<(NPATHS * NDH8 + 255) / 256, 256>>>(q_sqrt, od_of_path);
    k_out<<<NLINKS, NDH>>>(X, log_alpha, beta_raw, kcap, out);
}